// round 3
// baseline (speedup 1.0000x reference)
#include <cuda_runtime.h>
#include <cstdint>
#include <cstddef>

#define NB   128      // batches
#define NT   2048     // tokens per batch
#define NH   64       // hidden / features
#define NS   64       // segments

// ---------------- scratch (device globals: allocation-free) ----------------
__device__ float d_hA[(size_t)NB * NH * NT];   // hT of layer0 output: [b][f][n]
__device__ float d_hB[(size_t)NB * NH * NT];   // hT of layer1 output: [b][f][n]
__device__ float d_G [(size_t)NB * NS * NH];   // G[b][seg][f] = agg @ W_next_bottom
__device__ float d_agg[(size_t)NB * NS * NH];  // final layer-2 agg: [b][seg][f]
__device__ unsigned char d_cl[(size_t)NB * NT];
__device__ int d_is32;

typedef unsigned long long u64;

__device__ __forceinline__ u64 pack2(float lo, float hi) {
    u64 r; asm("mov.b64 %0, {%1, %2};" : "=l"(r) : "f"(lo), "f"(hi)); return r;
}
__device__ __forceinline__ void unpack2(u64 v, float& lo, float& hi) {
    asm("mov.b64 {%0, %1}, %2;" : "=f"(lo), "=f"(hi) : "l"(v));
}
__device__ __forceinline__ u64 fma2(u64 a, u64 b, u64 c) {
    u64 d; asm("fma.rn.f32x2 %0, %1, %2, %3;" : "=l"(d) : "l"(a), "l"(b), "l"(c)); return d;
}
__device__ __forceinline__ u64 add2(u64 a, u64 b) {
    u64 d; asm("add.rn.f32x2 %0, %1, %2;" : "=l"(d) : "l"(a), "l"(b)); return d;
}

// ---------------- cluster dtype sniff + convert ----------------
// jnp.int64 may silently be int32 if x64 is disabled. Distinguish: viewed as
// int32 words, an int64 buffer of values in [0,64) has ALL odd words == 0.
__global__ void k_init() { d_is32 = 0; }

__global__ void k_scan(const int* __restrict__ cl) {
    int i = blockIdx.x * blockDim.x + threadIdx.x;   // 131072 threads
    int idx = 2 * i + 1;
    if (idx < NB * NT) {
        if (cl[idx] != 0) d_is32 = 1;   // racy same-value store: deterministic
    }
}

__global__ void k_conv(const int* __restrict__ cl32, const long long* __restrict__ cl64) {
    int n = blockIdx.x * blockDim.x + threadIdx.x;
    if (n < NB * NT) {
        if (d_is32) d_cl[n] = (unsigned char)cl32[n];
        else        d_cl[n] = (unsigned char)(int)cl64[n];
    }
}

// ---------------- fused layer kernel ----------------
// LAYER 0: in = x [B][N][8], K=8, no G-gather, writes d_hA, makes G (Wnb=W1_bot)
// LAYER 1: in = d_hA [b][f][n], K=64, gathers d_G, writes d_hB, makes G (Wnb=W2_bot)
// LAYER 2: in = d_hB, K=64, gathers d_G, writes d_agg only (h2 never materialized)
template <int LAYER>
__global__ __launch_bounds__(512, 1)
void k_layer(const float* __restrict__ x,
             const float* __restrict__ Wtop,   // [CIN][64] row-major (k-major)
             const float* __restrict__ bias,
             const float* __restrict__ gam,
             const float* __restrict__ bet,
             const float* __restrict__ Wnb)    // next layer's W[64:128][:] (unused layer 2)
{
    constexpr int  CIN     = (LAYER == 0) ? 8 : 64;
    constexpr bool HAS_G   = (LAYER != 0);
    constexpr bool WRITE_H = (LAYER != 2);
    constexpr bool MAKE_G  = (LAYER != 2);
    constexpr bool WRITE_A = (LAYER == 2);

    __shared__ __align__(16) float    sW [CIN * NH];                  // 2KB or 16KB
    __shared__ __align__(16) float    sBG[HAS_G ? (NS * NH) : NH];    // bias (+G), swizzled
    __shared__               unsigned sAgg[NS * NH];                  // bit-max, swizzled

    const int b   = blockIdx.x;
    const int tid = threadIdx.x;

    for (int i = tid; i < CIN * NH; i += 512) sW[i] = Wtop[i];
    for (int i = tid; i < NS * NH; i += 512) sAgg[i] = 0u;
    if (HAS_G) {
        const float* gin = d_G + (size_t)b * NS * NH;
        for (int i = tid; i < NS * NH; i += 512) {
            int seg = i >> 6, f = i & 63;
            // swizzle by 4*seg: keeps 16B vector alignment, spreads banks
            sBG[seg * 64 + ((f + 4 * seg) & 63)] = bias[f] + gin[i];
        }
    } else {
        if (tid < NH) sBG[tid] = bias[tid];
    }
    __syncthreads();

    const int warp = tid >> 5, lane = tid & 31;
    const float* inp = (LAYER == 0) ? x : ((LAYER == 1) ? d_hA : d_hB);
    float* hOut = (LAYER == 0) ? d_hA : d_hB;

    for (int t = 0; t < NT / 512; t++) {
        const int token = warp * 128 + t * 32 + lane;
        const int seg   = d_cl[b * NT + token];

        u64 a[32];
        if (HAS_G) {
            const int sb = seg * 64, sh = (seg * 4) & 63;
            #pragma unroll
            for (int j = 0; j < 16; j++) {
                ulonglong2 v = *(const ulonglong2*)&sBG[sb + ((j * 4 + sh) & 63)];
                a[2 * j] = v.x; a[2 * j + 1] = v.y;
            }
        } else {
            #pragma unroll
            for (int j = 0; j < 16; j++) {
                ulonglong2 v = *(const ulonglong2*)&sBG[j * 4];
                a[2 * j] = v.x; a[2 * j + 1] = v.y;
            }
        }

        if (LAYER == 0) {
            const float4* xp = (const float4*)(x + ((size_t)b * NT + token) * 8);
            float4 x0 = __ldg(xp), x1 = __ldg(xp + 1);
            float xv[8] = {x0.x, x0.y, x0.z, x0.w, x1.x, x1.y, x1.z, x1.w};
            #pragma unroll
            for (int k = 0; k < 8; k++) {
                u64 hk = pack2(xv[k], xv[k]);
                const ulonglong2* wr = (const ulonglong2*)&sW[k * 64];
                #pragma unroll
                for (int j = 0; j < 16; j++) {
                    ulonglong2 w = wr[j];
                    a[2 * j]     = fma2(hk, w.x, a[2 * j]);
                    a[2 * j + 1] = fma2(hk, w.y, a[2 * j + 1]);
                }
            }
        } else {
            const float* ip = inp + (size_t)b * NH * NT + token;
            #pragma unroll 8
            for (int k = 0; k < 64; k++) {
                float hv = __ldg(ip + (size_t)k * NT);
                u64 hk = pack2(hv, hv);
                const ulonglong2* wr = (const ulonglong2*)&sW[k * 64];
                #pragma unroll
                for (int j = 0; j < 16; j++) {
                    ulonglong2 w = wr[j];
                    a[2 * j]     = fma2(hk, w.x, a[2 * j]);
                    a[2 * j + 1] = fma2(hk, w.y, a[2 * j + 1]);
                }
            }
        }

        // ---- LayerNorm + affine + ReLU (all 64 values live in this lane) ----
        u64 s = a[0];
        #pragma unroll
        for (int j = 1; j < 32; j++) s = add2(s, a[j]);
        float se, so; unpack2(s, se, so);
        const float mu = (se + so) * (1.0f / 64.0f);
        const u64 nmu = pack2(-mu, -mu);
        u64 q = 0;
        #pragma unroll
        for (int j = 0; j < 32; j++) { u64 dd = add2(a[j], nmu); q = fma2(dd, dd, q); }
        float qe, qo; unpack2(q, qe, qo);
        const float var = (qe + qo) * (1.0f / 64.0f);
        const float rs  = rsqrtf(var + 1e-5f);

        float* ho = hOut + (size_t)b * NH * NT + token;
        #pragma unroll
        for (int j = 0; j < 32; j++) {
            float lo, hi; unpack2(a[j], lo, hi);
            const int f0 = 2 * j;
            float v0 = fmaxf(fmaf((lo - mu) * rs, __ldg(gam + f0),     __ldg(bet + f0)),     0.0f);
            float v1 = fmaxf(fmaf((hi - mu) * rs, __ldg(gam + f0 + 1), __ldg(bet + f0 + 1)), 0.0f);
            if (WRITE_H) {
                ho[(size_t)f0 * NT]       = v0;
                ho[(size_t)(f0 + 1) * NT] = v1;
            }
            // nonneg floats: uint bit-pattern order == float order; init 0 == empty->0
            atomicMax(&sAgg[seg * 64 + ((f0 + seg) & 63)],     __float_as_uint(v0));
            atomicMax(&sAgg[seg * 64 + ((f0 + 1 + seg) & 63)], __float_as_uint(v1));
        }
    }
    __syncthreads();

    if (MAKE_G) {
        // G[b][seg][f] = agg[b][seg][:] @ Wnb   (64x64x64, trivial)
        const int seg = tid >> 3;
        const int f0  = (tid & 7) * 8;
        float acc[8];
        #pragma unroll
        for (int u = 0; u < 8; u++) acc[u] = 0.0f;
        #pragma unroll 8
        for (int k = 0; k < 64; k++) {
            float av = __uint_as_float(sAgg[seg * 64 + ((k + seg) & 63)]);
            const float4* wp = (const float4*)(Wnb + k * 64 + f0);
            float4 wa = __ldg(wp), wb = __ldg(wp + 1);
            acc[0] += av * wa.x; acc[1] += av * wa.y; acc[2] += av * wa.z; acc[3] += av * wa.w;
            acc[4] += av * wb.x; acc[5] += av * wb.y; acc[6] += av * wb.z; acc[7] += av * wb.w;
        }
        float* gp = d_G + ((size_t)b * NS + seg) * NH + f0;
        #pragma unroll
        for (int u = 0; u < 8; u++) gp[u] = acc[u];
    }

    if (WRITE_A) {
        for (int i = tid; i < NS * NH; i += 512) {
            int seg = i >> 6, f = i & 63;
            d_agg[(size_t)b * NS * NH + i] = __uint_as_float(sAgg[seg * 64 + ((f + seg) & 63)]);
        }
    }
}

// ---------------- final: out = tile(agg2, 2) / L2norm-over-segments ----------------
__global__ void k_final(float* __restrict__ out) {
    __shared__ float sInv[64];
    const int b = blockIdx.x, tid = threadIdx.x;
    const float* agg = d_agg + (size_t)b * NS * NH;
    if (tid < 64) {
        float ssum = 0.0f;
        const float* p = agg + tid;
        #pragma unroll 8
        for (int c = 0; c < NS; c++) { float v = p[c * NH]; ssum = fmaf(v, v, ssum); }
        float nrm = sqrtf(ssum);
        sInv[tid] = 1.0f / fmaxf(nrm, 1e-12f);
    }
    __syncthreads();
    for (int i = tid; i < NS * 128; i += blockDim.x) {
        int c = i >> 7, f = i & 127, f6 = f & 63;
        out[(size_t)b * NS * 128 + i] = agg[c * NH + f6] * sInv[f6];
    }
}

// ---------------- launch ----------------
extern "C" void kernel_launch(void* const* d_in, const int* in_sizes, int n_in,
                              void* d_out, int out_size) {
    (void)in_sizes; (void)n_in; (void)out_size;
    const float* x     = (const float*)d_in[0];
    const void*  clraw = d_in[1];
    const float* W0 = (const float*)d_in[2];
    const float* b0 = (const float*)d_in[3];
    const float* g0 = (const float*)d_in[4];
    const float* be0 = (const float*)d_in[5];
    const float* W1 = (const float*)d_in[6];
    const float* b1 = (const float*)d_in[7];
    const float* g1 = (const float*)d_in[8];
    const float* be1 = (const float*)d_in[9];
    const float* W2 = (const float*)d_in[10];
    const float* b2 = (const float*)d_in[11];
    const float* g2 = (const float*)d_in[12];
    const float* be2 = (const float*)d_in[13];
    float* out = (float*)d_out;

    k_init<<<1, 1>>>();
    k_scan<<<512, 256>>>((const int*)clraw);
    k_conv<<<(NB * NT + 511) / 512, 512>>>((const int*)clraw, (const long long*)clraw);

    // W layout: [K][H] row-major. Top = rows 0..63, bottom = rows 64..127.
    k_layer<0><<<NB, 512>>>(x, W0, b0, g0, be0, W1 + 64 * 64);
    k_layer<1><<<NB, 512>>>(x, W1, b1, g1, be1, W2 + 64 * 64);
    k_layer<2><<<NB, 512>>>(x, W2, b2, g2, be2, nullptr);

    k_final<<<NB, 256>>>(out);
}

// round 5
// speedup vs baseline: 1.6096x; 1.6096x over previous
#include <cuda_runtime.h>
#include <cuda_bf16.h>
#include <cstdint>
#include <cstddef>

#define NB 128
#define NT 2048
#define NS 64

// ---------------- dynamic smem layout (bytes) ----------------
#define OFF_BF_HI1 0          // W1 B-frags hi : 2048 uint2 = 16KB
#define OFF_BF_LO1 16384
#define OFF_BF_HI2 32768
#define OFF_BF_LO2 49152
#define OFF_W0P    65536      // 256 float2 = 2KB
#define OFF_GBP    67584      // 3 layers x 32 float4 = 1536B
#define OFF_BG2    69120      // 64 segs x 68 floats = 17408B
#define OFF_AGG    86528      // 64x64 u32 = 16KB
#define OFF_INV    102912     // 64 floats
#define SMEM_TOTAL 103168

// ---------------- device scratch ----------------
__device__ unsigned int d_hA[(size_t)NB * 64 * 2048];   // frag images layer0->1
__device__ unsigned int d_hB[(size_t)NB * 64 * 2048];   // frag images layer1->2
__device__ unsigned char d_cl[(size_t)NB * NT];
__device__ int d_is32;

// ---------------- helpers ----------------
__device__ __forceinline__ void bsplit(float v, uint32_t& h, uint32_t& l) {
    __nv_bfloat16 bh = __float2bfloat16(v);
    __nv_bfloat16 bl = __float2bfloat16(v - __bfloat162float(bh));
    h = (uint32_t)__bfloat16_as_ushort(bh);
    l = (uint32_t)__bfloat16_as_ushort(bl);
}
__device__ __forceinline__ uint32_t packbf(uint32_t lo16, uint32_t hi16) {
    return lo16 | (hi16 << 16);
}
__device__ __forceinline__ void mma16816(float* d, uint32_t a0, uint32_t a1,
                                         uint32_t a2, uint32_t a3,
                                         uint32_t b0, uint32_t b1) {
    asm volatile(
        "mma.sync.aligned.m16n8k16.row.col.f32.bf16.bf16.f32 "
        "{%0,%1,%2,%3}, {%4,%5,%6,%7}, {%8,%9}, {%0,%1,%2,%3};"
        : "+f"(d[0]), "+f"(d[1]), "+f"(d[2]), "+f"(d[3])
        : "r"(a0), "r"(a1), "r"(a2), "r"(a3), "r"(b0), "r"(b1));
}

// ---------------- cluster dtype sniff + convert ----------------
__global__ void k_init() { d_is32 = 0; }
__global__ void k_scan(const int* __restrict__ cl) {
    int i = blockIdx.x * blockDim.x + threadIdx.x;
    int idx = 2 * i + 1;
    if (idx < NB * NT) { if (cl[idx] != 0) d_is32 = 1; }
}
__global__ void k_conv(const int* __restrict__ c32, const long long* __restrict__ c64) {
    int n = blockIdx.x * blockDim.x + threadIdx.x;
    if (n < NB * NT) d_cl[n] = d_is32 ? (unsigned char)c32[n] : (unsigned char)(int)c64[n];
}

// ---------------- shared epilogue: +BG, LN, affine, ReLU, agg, frag-store ----------------
// acc[m][nt][q]: q0=(row g+16m, col 2tg), q1=(g+16m, 2tg+1), q2=(g+8+16m, 2tg), q3=odd
__device__ __forceinline__ void epilogue(float (&acc)[2][8][4], const int* segs,
                                         int layer, char* sm, int lane,
                                         uint4* dst /* null = no frag store */) {
    const int tg = lane & 3;
    float*        sBG  = (float*)(sm + OFF_BG2);          // stride 68 floats per seg
    const float4* sGBp = (const float4*)(sm + OFF_GBP) + layer * 32;
    unsigned*     sAgg = (unsigned*)(sm + OFF_AGG);

    // add bias (+ gathered G) BEFORE LayerNorm
    #pragma unroll
    for (int r = 0; r < 4; r++) {
        const int m = r >> 1, rh = r & 1;
        const float* bgrow = sBG + segs[r] * 68 + tg * 2;
        #pragma unroll
        for (int nt = 0; nt < 8; nt++) {
            float2 bg = *(const float2*)(bgrow + nt * 8);
            acc[m][nt][rh * 2]     += bg.x;
            acc[m][nt][rh * 2 + 1] += bg.y;
        }
    }
    // LayerNorm stats via quad shuffles (quad = same 4 token rows, disjoint cols)
    float mu[4], rs[4];
    #pragma unroll
    for (int r = 0; r < 4; r++) {
        const int m = r >> 1, rh = r & 1;
        float s = 0.f;
        #pragma unroll
        for (int nt = 0; nt < 8; nt++) s += acc[m][nt][rh * 2] + acc[m][nt][rh * 2 + 1];
        s += __shfl_xor_sync(0xffffffffu, s, 1);
        s += __shfl_xor_sync(0xffffffffu, s, 2);
        mu[r] = s * (1.0f / 64.0f);
        float q = 0.f;
        #pragma unroll
        for (int nt = 0; nt < 8; nt++) {
            float d0 = acc[m][nt][rh * 2]     - mu[r];
            float d1 = acc[m][nt][rh * 2 + 1] - mu[r];
            q = fmaf(d0, d0, q); q = fmaf(d1, d1, q);
        }
        q += __shfl_xor_sync(0xffffffffu, q, 1);
        q += __shfl_xor_sync(0xffffffffu, q, 2);
        rs[r] = rsqrtf(q * (1.0f / 64.0f) + 1e-5f);
    }
    // affine + relu + conditional segment max + optional frag store
    #pragma unroll
    for (int m = 0; m < 2; m++) {
        #pragma unroll
        for (int ntp = 0; ntp < 4; ntp++) {
            uint32_t hi4[4], lo4[4];
            #pragma unroll
            for (int q2 = 0; q2 < 2; q2++) {
                const int nt = 2 * ntp + q2;
                float4 gb = sGBp[nt * 4 + tg];
                const int c0 = nt * 8 + tg * 2;
                #pragma unroll
                for (int rh = 0; rh < 2; rh++) {
                    const int r = m * 2 + rh;
                    float v0 = fmaxf(fmaf((acc[m][nt][rh * 2]     - mu[r]) * rs[r], gb.x, gb.y), 0.f);
                    float v1 = fmaxf(fmaf((acc[m][nt][rh * 2 + 1] - mu[r]) * rs[r], gb.z, gb.w), 0.f);
                    uint32_t u0 = __float_as_uint(v0), u1 = __float_as_uint(v1);
                    unsigned* s0 = &sAgg[segs[r] * 64 + c0];
                    if (u0 > s0[0]) atomicMax(s0,     u0);
                    if (u1 > s0[1]) atomicMax(s0 + 1, u1);
                    if (dst) {
                        uint32_t h0, l0, h1, l1;
                        bsplit(v0, h0, l0); bsplit(v1, h1, l1);
                        hi4[q2 * 2 + rh] = packbf(h0, h1);
                        lo4[q2 * 2 + rh] = packbf(l0, l1);
                    }
                }
            }
            if (dst) {
                dst[(m * 4 + ntp) * 32 + lane]       = *(uint4*)hi4;
                dst[(8 + m * 4 + ntp) * 32 + lane]   = *(uint4*)lo4;
            }
        }
    }
}

// G[seg][f] = agg[seg] @ Wbot ; write bias_next + G into sBG (stride 68)
__device__ __forceinline__ void make_G(const float* __restrict__ Wbot,
                                       const float* __restrict__ bnext,
                                       char* sm, int tid) {
    unsigned* sAgg = (unsigned*)(sm + OFF_AGG);
    float*    sBG  = (float*)(sm + OFF_BG2);
    const int seg = tid >> 3, f0 = (tid & 7) * 8;
    float a8[8];
    #pragma unroll
    for (int u = 0; u < 8; u++) a8[u] = 0.f;
    #pragma unroll 8
    for (int k = 0; k < 64; k++) {
        float av = __uint_as_float(sAgg[seg * 64 + k]);
        float4 wa = __ldg((const float4*)(Wbot + k * 64 + f0));
        float4 wb = __ldg((const float4*)(Wbot + k * 64 + f0 + 4));
        a8[0] = fmaf(av, wa.x, a8[0]); a8[1] = fmaf(av, wa.y, a8[1]);
        a8[2] = fmaf(av, wa.z, a8[2]); a8[3] = fmaf(av, wa.w, a8[3]);
        a8[4] = fmaf(av, wb.x, a8[4]); a8[5] = fmaf(av, wb.y, a8[5]);
        a8[6] = fmaf(av, wb.z, a8[6]); a8[7] = fmaf(av, wb.w, a8[7]);
    }
    #pragma unroll
    for (int j = 0; j < 8; j++)
        sBG[seg * 68 + f0 + j] = bnext[f0 + j] + a8[j];
}

// ---------------- the fused kernel ----------------
__global__ __launch_bounds__(512, 1)
void k_fused(const float* __restrict__ x,
             const float* __restrict__ W0, const float* __restrict__ bs0,
             const float* __restrict__ gm0, const float* __restrict__ bt0,
             const float* __restrict__ W1, const float* __restrict__ bs1,
             const float* __restrict__ gm1, const float* __restrict__ bt1,
             const float* __restrict__ W2, const float* __restrict__ bs2,
             const float* __restrict__ gm2, const float* __restrict__ bt2,
             float* __restrict__ out)
{
    extern __shared__ char sm[];
    uint2*    sBfHi1 = (uint2*)(sm + OFF_BF_HI1);
    uint2*    sBfLo1 = (uint2*)(sm + OFF_BF_LO1);
    uint2*    sBfHi2 = (uint2*)(sm + OFF_BF_HI2);
    uint2*    sBfLo2 = (uint2*)(sm + OFF_BF_LO2);
    float2*   sW0p   = (float2*)(sm + OFF_W0P);
    float4*   sGBp   = (float4*)(sm + OFF_GBP);
    float*    sBG    = (float*)(sm + OFF_BG2);
    unsigned* sAgg   = (unsigned*)(sm + OFF_AGG);
    float*    sInv   = (float*)(sm + OFF_INV);

    const int b = blockIdx.x, tid = threadIdx.x;
    const int lane = tid & 31, warp = tid >> 5;
    const int tg = lane & 3, g = lane >> 2;

    // ---- build W1/W2 B-fragments (hi/lo), 2048 frag-slots each ----
    for (int i = tid; i < 2048; i += 512) {
        const int l2 = i & 31, nt = (i >> 5) & 7, kt = i >> 8;
        const int tg2 = l2 & 3, g2 = l2 >> 2;
        const int k0 = kt * 16 + tg2 * 2, n = nt * 8 + g2;
        uint32_t h00, l00, h01, l01, h10, l10, h11, l11;
        bsplit(W1[k0 * 64 + n], h00, l00);       bsplit(W1[(k0 + 1) * 64 + n], h01, l01);
        bsplit(W1[(k0 + 8) * 64 + n], h10, l10); bsplit(W1[(k0 + 9) * 64 + n], h11, l11);
        sBfHi1[i] = make_uint2(packbf(h00, h01), packbf(h10, h11));
        sBfLo1[i] = make_uint2(packbf(l00, l01), packbf(l10, l11));
        bsplit(W2[k0 * 64 + n], h00, l00);       bsplit(W2[(k0 + 1) * 64 + n], h01, l01);
        bsplit(W2[(k0 + 8) * 64 + n], h10, l10); bsplit(W2[(k0 + 9) * 64 + n], h11, l11);
        sBfHi2[i] = make_uint2(packbf(h00, h01), packbf(h10, h11));
        sBfLo2[i] = make_uint2(packbf(l00, l01), packbf(l10, l11));
    }
    // ---- W0 in frag-col order: sW0p[(k*8+nt)*4+tg] = (W0[k][c0], W0[k][c0+1]) ----
    if (tid < 256) {
        const int k = tid >> 5, nt = (tid >> 2) & 7, tg2 = tid & 3;
        const int c0 = nt * 8 + tg2 * 2;
        sW0p[tid] = make_float2(W0[k * 64 + c0], W0[k * 64 + c0 + 1]);
    }
    // ---- gamma/beta frag order for 3 layers ----
    if (tid < 96) {
        const int l = tid >> 5, p = tid & 31, nt = p >> 2, tg2 = p & 3;
        const int c0 = nt * 8 + tg2 * 2;
        const float* gl = (l == 0) ? gm0 : (l == 1) ? gm1 : gm2;
        const float* el = (l == 0) ? bt0 : (l == 1) ? bt1 : bt2;
        sGBp[tid] = make_float4(gl[c0], el[c0], gl[c0 + 1], el[c0 + 1]);
    }
    // ---- layer0 BG = bias0 replicated over segs; zero agg ----
    for (int i = tid; i < NS * 64; i += 512) {
        sBG[(i >> 6) * 68 + (i & 63)] = bs0[i & 63];
        sAgg[i] = 0u;
    }
    __syncthreads();

    const unsigned char* clb = d_cl + (size_t)b * NT;

    // ================= layer 0 (scalar fp32, K=8) =================
    for (int pass = 0; pass < 4; pass++) {
        const int tile = pass * 16 + warp;
        const int tbase = tile * 32;
        float acc[2][8][4];
        #pragma unroll
        for (int m = 0; m < 2; m++)
            #pragma unroll
            for (int nt = 0; nt < 8; nt++)
                #pragma unroll
                for (int q = 0; q < 4; q++) acc[m][nt][q] = 0.f;
        float xr[4][8];
        #pragma unroll
        for (int r = 0; r < 4; r++) {
            const float4* xp = (const float4*)(x + ((size_t)b * NT + tbase + g + 8 * r) * 8);
            float4 xa = __ldg(xp), xb = __ldg(xp + 1);
            xr[r][0] = xa.x; xr[r][1] = xa.y; xr[r][2] = xa.z; xr[r][3] = xa.w;
            xr[r][4] = xb.x; xr[r][5] = xb.y; xr[r][6] = xb.z; xr[r][7] = xb.w;
        }
        #pragma unroll
        for (int k = 0; k < 8; k++) {
            #pragma unroll
            for (int nt = 0; nt < 8; nt++) {
                float2 w = sW0p[(k * 8 + nt) * 4 + tg];
                #pragma unroll
                for (int r = 0; r < 4; r++) {
                    const int m = r >> 1, rh = r & 1;
                    acc[m][nt][rh * 2]     = fmaf(xr[r][k], w.x, acc[m][nt][rh * 2]);
                    acc[m][nt][rh * 2 + 1] = fmaf(xr[r][k], w.y, acc[m][nt][rh * 2 + 1]);
                }
            }
        }
        int segs[4];
        #pragma unroll
        for (int r = 0; r < 4; r++) segs[r] = clb[tbase + g + 8 * r];
        uint4* dst = (uint4*)(d_hA + ((size_t)b * 64 + tile) * 2048);
        epilogue(acc, segs, 0, sm, lane, dst);
    }
    __syncthreads();
    make_G(W1 + 64 * 64, bs1, sm, tid);
    __syncthreads();
    for (int i = tid; i < NS * 64; i += 512) sAgg[i] = 0u;
    __syncthreads();

    // ================= layers 1 & 2 (bf16 hi/lo mma) =================
    #pragma unroll 1
    for (int L = 1; L <= 2; L++) {
        const uint2* bfHi = (L == 1) ? sBfHi1 : sBfHi2;
        const uint2* bfLo = (L == 1) ? sBfLo1 : sBfLo2;
        const unsigned int* hsrc = (L == 1) ? d_hA : d_hB;
        for (int pass = 0; pass < 4; pass++) {
            const int tile = pass * 16 + warp;
            const int tbase = tile * 32;
            const uint4* src = (const uint4*)(hsrc + ((size_t)b * 64 + tile) * 2048);
            float acc[2][8][4];
            #pragma unroll
            for (int m = 0; m < 2; m++)
                #pragma unroll
                for (int nt = 0; nt < 8; nt++)
                    #pragma unroll
                    for (int q = 0; q < 4; q++) acc[m][nt][q] = 0.f;
            #pragma unroll
            for (int kt = 0; kt < 4; kt++) {
                uint4 ah0 = src[(kt)      * 32 + lane];   // m0 hi
                uint4 ah1 = src[(4 + kt)  * 32 + lane];   // m1 hi
                uint4 al0 = src[(8 + kt)  * 32 + lane];   // m0 lo
                uint4 al1 = src[(12 + kt) * 32 + lane];   // m1 lo
                #pragma unroll
                for (int nt = 0; nt < 8; nt++) {
                    uint2 bh = bfHi[(kt * 8 + nt) * 32 + lane];
                    uint2 bl = bfLo[(kt * 8 + nt) * 32 + lane];
                    mma16816(acc[0][nt], ah0.x, ah0.y, ah0.z, ah0.w, bh.x, bh.y);
                    mma16816(acc[0][nt], ah0.x, ah0.y, ah0.z, ah0.w, bl.x, bl.y);
                    mma16816(acc[0][nt], al0.x, al0.y, al0.z, al0.w, bh.x, bh.y);
                    mma16816(acc[1][nt], ah1.x, ah1.y, ah1.z, ah1.w, bh.x, bh.y);
                    mma16816(acc[1][nt], ah1.x, ah1.y, ah1.z, ah1.w, bl.x, bl.y);
                    mma16816(acc[1][nt], al1.x, al1.y, al1.z, al1.w, bh.x, bh.y);
                }
            }
            int segs[4];
            #pragma unroll
            for (int r = 0; r < 4; r++) segs[r] = clb[tbase + g + 8 * r];
            uint4* dst = (L == 1) ? (uint4*)(d_hB + ((size_t)b * 64 + tile) * 2048) : (uint4*)0;
            epilogue(acc, segs, L, sm, lane, dst);
        }
        __syncthreads();
        if (L == 1) {
            make_G(W2 + 64 * 64, bs2, sm, tid);
            __syncthreads();
            for (int i = tid; i < NS * 64; i += 512) sAgg[i] = 0u;
            __syncthreads();
        }
    }

    // ================= final: tile(agg,2) / column L2 norm =================
    if (tid < 64) {
        float ss = 0.f;
        #pragma unroll 8
        for (int s2 = 0; s2 < NS; s2++) {
            float v = __uint_as_float(sAgg[s2 * 64 + tid]);
            ss = fmaf(v, v, ss);
        }
        sInv[tid] = 1.0f / fmaxf(sqrtf(ss), 1e-12f);
    }
    __syncthreads();
    for (int i = tid; i < NS * 128; i += 512) {
        const int s2 = i >> 7, f6 = i & 63;
        out[(size_t)b * NS * 128 + i] = __uint_as_float(sAgg[s2 * 64 + f6]) * sInv[f6];
    }
}

// ---------------- launch ----------------
extern "C" void kernel_launch(void* const* d_in, const int* in_sizes, int n_in,
                              void* d_out, int out_size) {
    (void)in_sizes; (void)n_in; (void)out_size;
    const float* x  = (const float*)d_in[0];
    const void*  cl = d_in[1];
    const float* W0 = (const float*)d_in[2];
    const float* b0 = (const float*)d_in[3];
    const float* g0 = (const float*)d_in[4];
    const float* e0 = (const float*)d_in[5];
    const float* W1 = (const float*)d_in[6];
    const float* b1 = (const float*)d_in[7];
    const float* g1 = (const float*)d_in[8];
    const float* e1 = (const float*)d_in[9];
    const float* W2 = (const float*)d_in[10];
    const float* b2 = (const float*)d_in[11];
    const float* g2 = (const float*)d_in[12];
    const float* e2 = (const float*)d_in[13];
    float* out = (float*)d_out;

    static bool attr_done = false;
    if (!attr_done) {
        cudaFuncSetAttribute(k_fused, cudaFuncAttributeMaxDynamicSharedMemorySize, SMEM_TOTAL);
        attr_done = true;
    }

    k_init<<<1, 1>>>();
    k_scan<<<512, 256>>>((const int*)cl);
    k_conv<<<(NB * NT + 511) / 512, 512>>>((const int*)cl, (const long long*)cl);

    k_fused<<<NB, 512, SMEM_TOTAL>>>(x, W0, b0, g0, e0,
                                     W1, b1, g1, e1,
                                     W2, b2, g2, e2, out);
}

// round 6
// speedup vs baseline: 1.9074x; 1.1850x over previous
#include <cuda_runtime.h>
#include <cuda_bf16.h>
#include <cstdint>
#include <cstddef>

#define NB 128
#define NT 2048
#define NS 64

// ---------------- dynamic smem layout (bytes) ----------------
#define OFF_BF_HI1 0          // W1 B-frags hi : 2048 uint2 = 16KB
#define OFF_BF_LO1 16384
#define OFF_BF_HI2 32768
#define OFF_BF_LO2 49152
#define OFF_W0P    65536      // 256 float2 = 2KB
#define OFF_GBP    67584      // 3 layers x 32 float4 = 1536B
#define OFF_BG2    69120      // 64 segs x 66 floats = 16896B (stride 66: bank spread)
#define OFF_AGG    86016      // 64 segs x 65 u32 = 16640B (stride 65: bank spread)
#define OFF_INV    102656     // 64 floats
#define OFF_CL     102912     // 2048 u8 cluster ids
#define SMEM_TOTAL 104960

#define AGG_STR 65
#define BG_STR  66

// ---------------- device scratch ----------------
__device__ unsigned int d_hA[(size_t)NB * 64 * 2048];   // frag images layer0->1
__device__ unsigned int d_hB[(size_t)NB * 64 * 2048];   // frag images layer1->2
__device__ int d_is32;

// ---------------- helpers ----------------
__device__ __forceinline__ void bsplit(float v, uint32_t& h, uint32_t& l) {
    __nv_bfloat16 bh = __float2bfloat16(v);
    __nv_bfloat16 bl = __float2bfloat16(v - __bfloat162float(bh));
    h = (uint32_t)__bfloat16_as_ushort(bh);
    l = (uint32_t)__bfloat16_as_ushort(bl);
}
__device__ __forceinline__ uint32_t packbf(uint32_t lo16, uint32_t hi16) {
    return lo16 | (hi16 << 16);
}
__device__ __forceinline__ void mma16816(float* d, uint32_t a0, uint32_t a1,
                                         uint32_t a2, uint32_t a3,
                                         uint32_t b0, uint32_t b1) {
    asm volatile(
        "mma.sync.aligned.m16n8k16.row.col.f32.bf16.bf16.f32 "
        "{%0,%1,%2,%3}, {%4,%5,%6,%7}, {%8,%9}, {%0,%1,%2,%3};"
        : "+f"(d[0]), "+f"(d[1]), "+f"(d[2]), "+f"(d[3])
        : "r"(a0), "r"(a1), "r"(a2), "r"(a3), "r"(b0), "r"(b1));
}

// ---------------- cluster dtype sniff ----------------
__global__ void k_init() { d_is32 = 0; }
__global__ void k_scan(const int* __restrict__ cl) {
    int i = blockIdx.x * blockDim.x + threadIdx.x;
    int idx = 2 * i + 1;
    if (idx < NB * NT) { if (cl[idx] != 0) d_is32 = 1; }
}

// ---------------- shared epilogue: +BG, LN, affine, ReLU, agg, frag-store ----------------
// acc[m][nt][q]: q0=(row g+16m, col 2tg), q1=(g+16m, 2tg+1), q2=(g+8+16m, 2tg), q3=odd
__device__ __forceinline__ void epilogue(float (&acc)[2][8][4], const int* segs,
                                         int layer, char* sm, int lane,
                                         uint4* dst /* null = no frag store */) {
    const int tg = lane & 3;
    float*        sBG  = (float*)(sm + OFF_BG2);
    const float4* sGBp = (const float4*)(sm + OFF_GBP) + layer * 32;
    unsigned*     sAgg = (unsigned*)(sm + OFF_AGG);

    // add bias (+ gathered G) BEFORE LayerNorm
    #pragma unroll
    for (int r = 0; r < 4; r++) {
        const int m = r >> 1, rh = r & 1;
        const float* bgrow = sBG + segs[r] * BG_STR + tg * 2;
        #pragma unroll
        for (int nt = 0; nt < 8; nt++) {
            float2 bg = *(const float2*)(bgrow + nt * 8);
            acc[m][nt][rh * 2]     += bg.x;
            acc[m][nt][rh * 2 + 1] += bg.y;
        }
    }
    // LayerNorm stats via quad shuffles
    float mu[4], rs[4];
    #pragma unroll
    for (int r = 0; r < 4; r++) {
        const int m = r >> 1, rh = r & 1;
        float s = 0.f;
        #pragma unroll
        for (int nt = 0; nt < 8; nt++) s += acc[m][nt][rh * 2] + acc[m][nt][rh * 2 + 1];
        s += __shfl_xor_sync(0xffffffffu, s, 1);
        s += __shfl_xor_sync(0xffffffffu, s, 2);
        mu[r] = s * (1.0f / 64.0f);
        float q = 0.f;
        #pragma unroll
        for (int nt = 0; nt < 8; nt++) {
            float d0 = acc[m][nt][rh * 2]     - mu[r];
            float d1 = acc[m][nt][rh * 2 + 1] - mu[r];
            q = fmaf(d0, d0, q); q = fmaf(d1, d1, q);
        }
        q += __shfl_xor_sync(0xffffffffu, q, 1);
        q += __shfl_xor_sync(0xffffffffu, q, 2);
        rs[r] = rsqrtf(q * (1.0f / 64.0f) + 1e-5f);
    }
    // affine + relu + conditional segment max + optional frag store
    #pragma unroll
    for (int m = 0; m < 2; m++) {
        #pragma unroll
        for (int ntp = 0; ntp < 4; ntp++) {
            uint32_t hi4[4], lo4[4];
            #pragma unroll
            for (int q2 = 0; q2 < 2; q2++) {
                const int nt = 2 * ntp + q2;
                float4 gb = sGBp[nt * 4 + tg];
                const int c0 = nt * 8 + tg * 2;
                #pragma unroll
                for (int rh = 0; rh < 2; rh++) {
                    const int r = m * 2 + rh;
                    float v0 = fmaxf(fmaf((acc[m][nt][rh * 2]     - mu[r]) * rs[r], gb.x, gb.y), 0.f);
                    float v1 = fmaxf(fmaf((acc[m][nt][rh * 2 + 1] - mu[r]) * rs[r], gb.z, gb.w), 0.f);
                    uint32_t u0 = __float_as_uint(v0), u1 = __float_as_uint(v1);
                    unsigned* s0 = &sAgg[segs[r] * AGG_STR + c0];
                    if (u0 > s0[0]) atomicMax(s0,     u0);
                    if (u1 > s0[1]) atomicMax(s0 + 1, u1);
                    if (dst) {
                        uint32_t h0, l0, h1, l1;
                        bsplit(v0, h0, l0); bsplit(v1, h1, l1);
                        hi4[q2 * 2 + rh] = packbf(h0, h1);
                        lo4[q2 * 2 + rh] = packbf(l0, l1);
                    }
                }
            }
            if (dst) {
                dst[(m * 4 + ntp) * 32 + lane]       = *(uint4*)hi4;
                dst[(8 + m * 4 + ntp) * 32 + lane]   = *(uint4*)lo4;
            }
        }
    }
}

// G[seg][f] = agg[seg] @ Wbot ; write bias_next + G into sBG
__device__ __forceinline__ void make_G(const float* __restrict__ Wbot,
                                       const float* __restrict__ bnext,
                                       char* sm, int tid) {
    unsigned* sAgg = (unsigned*)(sm + OFF_AGG);
    float*    sBG  = (float*)(sm + OFF_BG2);
    const int seg = tid >> 3, f0 = (tid & 7) * 8;
    float a8[8];
    #pragma unroll
    for (int u = 0; u < 8; u++) a8[u] = 0.f;
    #pragma unroll 8
    for (int k = 0; k < 64; k++) {
        float av = __uint_as_float(sAgg[seg * AGG_STR + k]);
        float4 wa = __ldg((const float4*)(Wbot + k * 64 + f0));
        float4 wb = __ldg((const float4*)(Wbot + k * 64 + f0 + 4));
        a8[0] = fmaf(av, wa.x, a8[0]); a8[1] = fmaf(av, wa.y, a8[1]);
        a8[2] = fmaf(av, wa.z, a8[2]); a8[3] = fmaf(av, wa.w, a8[3]);
        a8[4] = fmaf(av, wb.x, a8[4]); a8[5] = fmaf(av, wb.y, a8[5]);
        a8[6] = fmaf(av, wb.z, a8[6]); a8[7] = fmaf(av, wb.w, a8[7]);
    }
    #pragma unroll
    for (int j = 0; j < 8; j++)
        sBG[seg * BG_STR + f0 + j] = bnext[f0 + j] + a8[j];
}

// ---------------- the fused kernel ----------------
__global__ __launch_bounds__(512, 1)
void k_fused(const float* __restrict__ x, const void* __restrict__ clraw,
             const float* __restrict__ W0, const float* __restrict__ bs0,
             const float* __restrict__ gm0, const float* __restrict__ bt0,
             const float* __restrict__ W1, const float* __restrict__ bs1,
             const float* __restrict__ gm1, const float* __restrict__ bt1,
             const float* __restrict__ W2, const float* __restrict__ bs2,
             const float* __restrict__ gm2, const float* __restrict__ bt2,
             float* __restrict__ out)
{
    extern __shared__ char sm[];
    uint2*         sBfHi1 = (uint2*)(sm + OFF_BF_HI1);
    uint2*         sBfLo1 = (uint2*)(sm + OFF_BF_LO1);
    uint2*         sBfHi2 = (uint2*)(sm + OFF_BF_HI2);
    uint2*         sBfLo2 = (uint2*)(sm + OFF_BF_LO2);
    float2*        sW0p   = (float2*)(sm + OFF_W0P);
    float4*        sGBp   = (float4*)(sm + OFF_GBP);
    float*         sBG    = (float*)(sm + OFF_BG2);
    unsigned*      sAgg   = (unsigned*)(sm + OFF_AGG);
    float*         sInv   = (float*)(sm + OFF_INV);
    unsigned char* sCl    = (unsigned char*)(sm + OFF_CL);

    const int b = blockIdx.x, tid = threadIdx.x;
    const int lane = tid & 31, warp = tid >> 5;
    const int tg = lane & 3, g = lane >> 2;

    // ---- cluster ids -> SMEM (dtype decided by sniff kernel) ----
    {
        const int is32 = d_is32;
        const int* c32 = (const int*)clraw;
        const long long* c64 = (const long long*)clraw;
        for (int i = tid; i < NT; i += 512) {
            int v = is32 ? c32[(size_t)b * NT + i] : (int)c64[(size_t)b * NT + i];
            sCl[i] = (unsigned char)v;
        }
    }
    // ---- build W1/W2 B-fragments (hi/lo) ----
    for (int i = tid; i < 2048; i += 512) {
        const int l2 = i & 31, nt = (i >> 5) & 7, kt = i >> 8;
        const int tg2 = l2 & 3, g2 = l2 >> 2;
        const int k0 = kt * 16 + tg2 * 2, n = nt * 8 + g2;
        uint32_t h00, l00, h01, l01, h10, l10, h11, l11;
        bsplit(W1[k0 * 64 + n], h00, l00);       bsplit(W1[(k0 + 1) * 64 + n], h01, l01);
        bsplit(W1[(k0 + 8) * 64 + n], h10, l10); bsplit(W1[(k0 + 9) * 64 + n], h11, l11);
        sBfHi1[i] = make_uint2(packbf(h00, h01), packbf(h10, h11));
        sBfLo1[i] = make_uint2(packbf(l00, l01), packbf(l10, l11));
        bsplit(W2[k0 * 64 + n], h00, l00);       bsplit(W2[(k0 + 1) * 64 + n], h01, l01);
        bsplit(W2[(k0 + 8) * 64 + n], h10, l10); bsplit(W2[(k0 + 9) * 64 + n], h11, l11);
        sBfHi2[i] = make_uint2(packbf(h00, h01), packbf(h10, h11));
        sBfLo2[i] = make_uint2(packbf(l00, l01), packbf(l10, l11));
    }
    // ---- W0 in frag-col order ----
    if (tid < 256) {
        const int k = tid >> 5, nt = (tid >> 2) & 7, tg2 = tid & 3;
        const int c0 = nt * 8 + tg2 * 2;
        sW0p[tid] = make_float2(W0[k * 64 + c0], W0[k * 64 + c0 + 1]);
    }
    // ---- gamma/beta frag order for 3 layers ----
    if (tid < 96) {
        const int l = tid >> 5, p = tid & 31, nt = p >> 2, tg2 = p & 3;
        const int c0 = nt * 8 + tg2 * 2;
        const float* gl = (l == 0) ? gm0 : (l == 1) ? gm1 : gm2;
        const float* el = (l == 0) ? bt0 : (l == 1) ? bt1 : bt2;
        sGBp[tid] = make_float4(gl[c0], el[c0], gl[c0 + 1], el[c0 + 1]);
    }
    // ---- layer0 BG = bias0 replicated; zero agg ----
    for (int i = tid; i < NS * 64; i += 512)
        sBG[(i >> 6) * BG_STR + (i & 63)] = bs0[i & 63];
    for (int i = tid; i < NS * AGG_STR; i += 512) sAgg[i] = 0u;
    __syncthreads();

    // ================= layer 0 (scalar fp32, K=8) =================
    for (int pass = 0; pass < 4; pass++) {
        const int tile = pass * 16 + warp;
        const int tbase = tile * 32;
        float acc[2][8][4];
        #pragma unroll
        for (int m = 0; m < 2; m++)
            #pragma unroll
            for (int nt = 0; nt < 8; nt++)
                #pragma unroll
                for (int q = 0; q < 4; q++) acc[m][nt][q] = 0.f;
        float xr[4][8];
        #pragma unroll
        for (int r = 0; r < 4; r++) {
            const float4* xp = (const float4*)(x + ((size_t)b * NT + tbase + g + 8 * r) * 8);
            float4 xa = __ldg(xp), xb = __ldg(xp + 1);
            xr[r][0] = xa.x; xr[r][1] = xa.y; xr[r][2] = xa.z; xr[r][3] = xa.w;
            xr[r][4] = xb.x; xr[r][5] = xb.y; xr[r][6] = xb.z; xr[r][7] = xb.w;
        }
        #pragma unroll
        for (int k = 0; k < 8; k++) {
            #pragma unroll
            for (int nt = 0; nt < 8; nt++) {
                float2 w = sW0p[(k * 8 + nt) * 4 + tg];
                #pragma unroll
                for (int r = 0; r < 4; r++) {
                    const int m = r >> 1, rh = r & 1;
                    acc[m][nt][rh * 2]     = fmaf(xr[r][k], w.x, acc[m][nt][rh * 2]);
                    acc[m][nt][rh * 2 + 1] = fmaf(xr[r][k], w.y, acc[m][nt][rh * 2 + 1]);
                }
            }
        }
        int segs[4];
        #pragma unroll
        for (int r = 0; r < 4; r++) segs[r] = sCl[tbase + g + 8 * r];
        uint4* dst = (uint4*)(d_hA + ((size_t)b * 64 + tile) * 2048);
        epilogue(acc, segs, 0, sm, lane, dst);
    }
    __syncthreads();
    make_G(W1 + 64 * 64, bs1, sm, tid);
    __syncthreads();
    for (int i = tid; i < NS * AGG_STR; i += 512) sAgg[i] = 0u;
    __syncthreads();

    // ================= layers 1 & 2 (bf16 hi/lo mma) =================
    #pragma unroll 1
    for (int L = 1; L <= 2; L++) {
        const uint2* bfHi = (L == 1) ? sBfHi1 : sBfHi2;
        const uint2* bfLo = (L == 1) ? sBfLo1 : sBfLo2;
        const unsigned int* hsrc = (L == 1) ? d_hA : d_hB;
        for (int pass = 0; pass < 4; pass++) {
            const int tile = pass * 16 + warp;
            const int tbase = tile * 32;
            const uint4* src = (const uint4*)(hsrc + ((size_t)b * 64 + tile) * 2048);
            float acc[2][8][4];
            #pragma unroll
            for (int m = 0; m < 2; m++)
                #pragma unroll
                for (int nt = 0; nt < 8; nt++)
                    #pragma unroll
                    for (int q = 0; q < 4; q++) acc[m][nt][q] = 0.f;
            #pragma unroll
            for (int kt = 0; kt < 4; kt++) {
                uint4 ah0 = src[(kt)      * 32 + lane];
                uint4 ah1 = src[(4 + kt)  * 32 + lane];
                uint4 al0 = src[(8 + kt)  * 32 + lane];
                uint4 al1 = src[(12 + kt) * 32 + lane];
                #pragma unroll
                for (int nt = 0; nt < 8; nt++) {
                    uint2 bh = bfHi[(kt * 8 + nt) * 32 + lane];
                    uint2 bl = bfLo[(kt * 8 + nt) * 32 + lane];
                    mma16816(acc[0][nt], ah0.x, ah0.y, ah0.z, ah0.w, bh.x, bh.y);
                    mma16816(acc[0][nt], ah0.x, ah0.y, ah0.z, ah0.w, bl.x, bl.y);
                    mma16816(acc[0][nt], al0.x, al0.y, al0.z, al0.w, bh.x, bh.y);
                    mma16816(acc[1][nt], ah1.x, ah1.y, ah1.z, ah1.w, bh.x, bh.y);
                    mma16816(acc[1][nt], ah1.x, ah1.y, ah1.z, ah1.w, bl.x, bl.y);
                    mma16816(acc[1][nt], al1.x, al1.y, al1.z, al1.w, bh.x, bh.y);
                }
            }
            int segs[4];
            #pragma unroll
            for (int r = 0; r < 4; r++) segs[r] = sCl[tbase + g + 8 * r];
            uint4* dst = (L == 1) ? (uint4*)(d_hB + ((size_t)b * 64 + tile) * 2048) : (uint4*)0;
            epilogue(acc, segs, L, sm, lane, dst);
        }
        __syncthreads();
        if (L == 1) {
            make_G(W2 + 64 * 64, bs2, sm, tid);
            __syncthreads();
            for (int i = tid; i < NS * AGG_STR; i += 512) sAgg[i] = 0u;
            __syncthreads();
        }
    }

    // ================= final: tile(agg,2) / column L2 norm =================
    if (tid < 64) {
        float ss = 0.f;
        #pragma unroll 8
        for (int s2 = 0; s2 < NS; s2++) {
            float v = __uint_as_float(sAgg[s2 * AGG_STR + tid]);
            ss = fmaf(v, v, ss);
        }
        sInv[tid] = 1.0f / fmaxf(sqrtf(ss), 1e-12f);
    }
    __syncthreads();
    for (int i = tid; i < NS * 128; i += 512) {
        const int s2 = i >> 7, f6 = i & 63;
        out[(size_t)b * NS * 128 + i] = __uint_as_float(sAgg[s2 * AGG_STR + f6]) * sInv[f6];
    }
}

// ---------------- launch ----------------
extern "C" void kernel_launch(void* const* d_in, const int* in_sizes, int n_in,
                              void* d_out, int out_size) {
    (void)in_sizes; (void)n_in; (void)out_size;
    const float* x  = (const float*)d_in[0];
    const void*  cl = d_in[1];
    const float* W0 = (const float*)d_in[2];
    const float* b0 = (const float*)d_in[3];
    const float* g0 = (const float*)d_in[4];
    const float* e0 = (const float*)d_in[5];
    const float* W1 = (const float*)d_in[6];
    const float* b1 = (const float*)d_in[7];
    const float* g1 = (const float*)d_in[8];
    const float* e1 = (const float*)d_in[9];
    const float* W2 = (const float*)d_in[10];
    const float* b2 = (const float*)d_in[11];
    const float* g2 = (const float*)d_in[12];
    const float* e2 = (const float*)d_in[13];
    float* out = (float*)d_out;

    static bool attr_done = false;
    if (!attr_done) {
        cudaFuncSetAttribute(k_fused, cudaFuncAttributeMaxDynamicSharedMemorySize, SMEM_TOTAL);
        attr_done = true;
    }

    k_init<<<1, 1>>>();
    k_scan<<<512, 256>>>((const int*)cl);

    k_fused<<<NB, 512, SMEM_TOTAL>>>(x, cl,
                                     W0, b0, g0, e0,
                                     W1, b1, g1, e1,
                                     W2, b2, g2, e2, out);
}